// round 12
// baseline (speedup 1.0000x reference)
#include <cuda_runtime.h>
#include <math.h>
#include <stdint.h>

#define NB 16
#define NT 2048
#define NC 256
#define NF 256
#define NU 512
#define NMEL 80
#define NOUTC 592           // 2*NC + NMEL
#define KTOT 768            // NC * 3 taps
#define BK 8
#define NPAIR 48            // 96 chunks as 48 pairs
#define UM2CAP 8192
#define EPS 1e-5f
#define AP2 260             // Ahl row pad in float2 (520 words, %32=8 -> conflict-free)
#define BP2 68              // Bhl row pad in float2 (136 words, %32=8)

// dynamic smem carve (bytes)
#define SM_AHL   0
#define SM_BHL   (4 * BK * AP2 * 8)                    // 66560
#define SM_TOTAL (SM_BHL + 4 * BK * BP2 * 8)           // 83968
// epilogue aliases (loop finished before use)
#define SM_XCH   0                                     // float[256][33] = 33792
#define SM_REDA  40960                                 // float[8][64]
#define SM_REDB  43008
#define SM_MVS   45056
#define SM_RVS   45312

// ---------------- static device scratch ----------------
__device__ int    g_starts[NB*NU];
__device__ int    g_dur[NB*NU];
__device__ int    g_nseg[NB];
__device__ int    g_umax;
__device__ float  g_cgv[NB*NC];
__device__ float  g_uc[NB*NC*NU];
__device__ float  g_up[NB*NC*NU];
__device__ float2 g_w1hl[NF*KTOT];      // conv1 weight tf32 (hi,lo)
__device__ float2 g_w2hl[NF*KTOT];      // conv2 weight tf32 (hi,lo)
__device__ float2 g_x0hl[NB*NC*NU];     // conv1 input split
__device__ float2 g_x1hl[NB*NF*NU];     // conv2 input split (LN1 out * mask)
__device__ int    g_dpred[NB*NU];
__device__ int    g_um2[NB*UM2CAP];

__device__ __forceinline__ unsigned f2tf32(float x) {
    unsigned r; asm("cvt.rna.tf32.f32 %0, %1;" : "=r"(r) : "f"(x)); return r;
}
__device__ __forceinline__ float2 split2(float x) {
    float h = __uint_as_float(f2tf32(x));
    return make_float2(h, __uint_as_float(f2tf32(x - h)));
}
__device__ __forceinline__ void mma_tf32(float* c, const unsigned* a,
                                         unsigned b0, unsigned b1) {
    asm("mma.sync.aligned.m16n8k8.row.col.f32.tf32.tf32.f32 "
        "{%0,%1,%2,%3}, {%4,%5,%6,%7}, {%8,%9}, {%0,%1,%2,%3};"
        : "+f"(c[0]), "+f"(c[1]), "+f"(c[2]), "+f"(c[3])
        : "r"(a[0]), "r"(a[1]), "r"(a[2]), "r"(a[3]), "r"(b0), "r"(b1));
}

// ---------------- kernel 0: zero um2 + umax ----------------
__global__ void k_zero(int Tn) {
    int i = blockIdx.x * blockDim.x + threadIdx.x;
    if (i == 0) g_umax = 0;
    if (i < NB * Tn) g_um2[i] = 0;
}

// ---------------- kernel 0b: precompute weight tf32 splits ----------------
__global__ void k_wsplit(const float* __restrict__ w1, const float* __restrict__ w2) {
    int i = blockIdx.x * blockDim.x + threadIdx.x;
    if (i < NF * KTOT) {
        g_w1hl[i] = split2(w1[i]);
        g_w2hl[i] = split2(w2[i]);
    }
}

// ---------------- kernel 1: fused dedup (blocks 0..15) + cond (blocks 16..31) ----------------
__global__ __launch_bounds__(1024) void k_prep(const int* __restrict__ ph,
                                               const float* __restrict__ g,
                                               const float* __restrict__ cw,
                                               const float* __restrict__ cb) {
    int blk = blockIdx.x;
    if (blk < NB) {
        int b = blk;
        const int* p = ph + (size_t)b * NT;
        int tid = threadIdx.x;
        int lane = tid & 31, wid = tid >> 5;
        int i0 = 2 * tid, i1 = 2 * tid + 1;
        int p0 = p[i0], p1 = p[i1];
        int pm1 = (i0 > 0) ? p[i0 - 1] : 0;
        int f0 = (i0 == 0) || (p0 != pm1);
        int f1 = (p1 != p0);
        int tsum = f0 + f1;
        int ws = tsum;
        #pragma unroll
        for (int o = 1; o < 32; o <<= 1) {
            int y = __shfl_up_sync(0xffffffffu, ws, o);
            if (lane >= o) ws += y;
        }
        __shared__ int wt[32];
        if (lane == 31) wt[wid] = ws;
        __syncthreads();
        if (wid == 0) {
            int t = wt[lane];
            #pragma unroll
            for (int o = 1; o < 32; o <<= 1) {
                int y = __shfl_up_sync(0xffffffffu, t, o);
                if (lane >= o) t += y;
            }
            wt[lane] = t;
        }
        __syncthreads();
        int base = (wid ? wt[wid - 1] : 0) + (ws - tsum);
        int incl0 = base + f0;
        int incl1 = base + f0 + f1;
        if (f0) g_starts[b * NU + incl0 - 1] = i0;
        if (f1) g_starts[b * NU + incl1 - 1] = i1;
        int ns = wt[31];
        __syncthreads();
        for (int u = tid; u < NU; u += 1024) {
            if (u < ns) {
                int st = g_starts[b * NU + u];
                int en = (u + 1 < ns) ? g_starts[b * NU + u + 1] : NT;
                g_dur[b * NU + u] = en - st;
            } else {
                g_dur[b * NU + u] = 0;
            }
        }
        if (tid == 0) {
            g_nseg[b] = ns;
            atomicMax(&g_umax, ns);
        }
    } else {
        int b = blk - NB;
        int c = threadIdx.x;
        __shared__ float gs[NC];
        if (c < NC) gs[c] = g[(size_t)b * NC + c];
        __syncthreads();
        if (c < NC) {
            float acc = 0.f;
            const float* row = cw + (size_t)c * NC;
            #pragma unroll 8
            for (int gi = 0; gi < NC; gi++) acc += row[gi] * gs[gi];
            g_cgv[b * NC + c] = acc + cb[c];
        }
    }
}

// ---------------- kernel 2: mean pool (4 channels / block) ----------------
__global__ __launch_bounds__(256) void k_pool(const float* __restrict__ ec,
                                              const float* __restrict__ ep) {
    int b  = blockIdx.y;
    int c0 = blockIdx.x * 4;
    bool isC = (c0 < NC);
    const float* base = isC ? ec + ((size_t)b * NC + c0) * NT
                            : ep + ((size_t)b * NC + (c0 - NC)) * NT;
    __shared__ float rows[4][NT];
    const float4* s4 = (const float4*)base;
    float4* r4 = (float4*)&rows[0][0];
    #pragma unroll
    for (int i = threadIdx.x; i < 4 * NT / 4; i += 256) r4[i] = s4[i];
    __syncthreads();
    int ns = g_nseg[b];
    for (int u = threadIdx.x; u < NU; u += 256) {
        float m[4] = {0.f, 0.f, 0.f, 0.f};
        if (u < ns) {
            int st = g_starts[b * NU + u];
            int d  = g_dur[b * NU + u];
            float inv = 1.f / (float)d;
            #pragma unroll
            for (int r = 0; r < 4; r++) {
                float s = 0.f;
                for (int i = 0; i < d; i++) s += rows[r][st + i];
                m[r] = s * inv;
            }
        }
        #pragma unroll
        for (int r = 0; r < 4; r++) {
            int cc = c0 + r;
            if (isC) {
                float cond = g_cgv[b * NC + cc];
                g_uc[((size_t)b * NC + cc) * NU + u] = m[r];
                float x0 = (u < ns) ? (m[r] + cond) : 0.f;
                g_x0hl[((size_t)b * NC + cc) * NU + u] = split2(x0);
            } else {
                g_up[((size_t)b * NC + (cc - NC)) * NU + u] = m[r];
            }
        }
    }
}

// ---------------- conv GEMM via 3xTF32 mma.sync, K-split warp-sets, precomputed splits --------
// 512 threads = 16 warps. Warp-set s=w>>3: set 0 accumulates even chunks, set 1 odd.
// Within a set, warp ww=w&7: rows ww*32..+31 (2 m16), all 64 cols (8 n8).
// W and X tf32 (hi,lo) precomputed in global; mainloop loader is pure LDG->STS.
// PHASE 0: X=g_x0hl, epilogue = bias+relu+LN1*mask -> split -> g_x1hl
// PHASE 1: X=g_x1hl, epilogue = bias+relu+LN2*mask -> proj -> ceil -> g_dpred
template<int PHASE>
__global__ __launch_bounds__(512) void k_conv(const float* __restrict__ bias,
                                              const float* __restrict__ gamma,
                                              const float* __restrict__ beta,
                                              const float* __restrict__ pw,
                                              const float* __restrict__ pb) {
    extern __shared__ char smraw[];
    float2 (*Ahl)[BK][AP2] = (float2 (*)[BK][AP2])(smraw + SM_AHL);
    float2 (*Bhl)[BK][BP2] = (float2 (*)[BK][BP2])(smraw + SM_BHL);
    float* Xch  = (float*)(smraw + SM_XCH);     // [256][33]
    float (*redA)[64] = (float (*)[64])(smraw + SM_REDA);
    float (*redB)[64] = (float (*)[64])(smraw + SM_REDB);
    float* mvs = (float*)(smraw + SM_MVS);
    float* rvs = (float*)(smraw + SM_RVS);

    int b  = blockIdx.y;
    int u0 = blockIdx.x * 64;
    int tid = threadIdx.x;
    int w  = tid >> 5;
    int l  = tid & 31;
    int s  = w >> 3;        // warp-set
    int ww = w & 7;         // warp within set
    int gq = l >> 2;        // 0..7
    int tq = l & 3;         // 0..3
    const float2* Whl = PHASE ? g_w2hl : g_w1hl;
    const float2* Xbhl = (PHASE ? g_x1hl : g_x0hl) + (size_t)b * NC * NU;

    float acc[2][8][4];
    #pragma unroll
    for (int i = 0; i < 2; i++)
        #pragma unroll
        for (int j = 0; j < 8; j++)
            #pragma unroll
            for (int r = 0; r < 4; r++) acc[i][j][r] = 0.f;

    // loaders (512 threads): A: row am, k-half akh per chunk; B: (bk, bn) per chunk
    int am  = tid & 255;
    int akh = tid >> 8;          // 0/1
    int bk  = tid >> 6;          // 0..7
    int bn  = tid & 63;
    float4 a0A, a0B, a1A, a1B;   // 4 float2 per chunk
    float2 b0v, b1v;

    auto loadG2 = [&](int pair) {
        int c0 = 2 * pair, c1 = c0 + 1;
        const float4* wr0 = (const float4*)&Whl[(size_t)am * KTOT + c0 * 8 + akh * 4];
        a0A = wr0[0]; a0B = wr0[1];
        const float4* wr1 = (const float4*)&Whl[(size_t)am * KTOT + c1 * 8 + akh * 4];
        a1A = wr1[0]; a1B = wr1[1];
        int kg0 = c0 * 8 + bk;
        int ch0 = kg0 / 3, tap0 = kg0 - 3 * ch0;
        int pos0 = u0 + bn + tap0 - 1;
        b0v = (pos0 >= 0 && pos0 < NU) ? Xbhl[(size_t)ch0 * NU + pos0] : make_float2(0.f, 0.f);
        int kg1 = c1 * 8 + bk;
        int ch1 = kg1 / 3, tap1 = kg1 - 3 * ch1;
        int pos1 = u0 + bn + tap1 - 1;
        b1v = (pos1 >= 0 && pos1 < NU) ? Xbhl[(size_t)ch1 * NU + pos1] : make_float2(0.f, 0.f);
    };
    auto storeS2 = [&](int pair) {
        int c0 = 2 * pair, c1 = c0 + 1;
        int f0 = c0 & 3, f1 = c1 & 3;
        Ahl[f0][akh * 4 + 0][am] = make_float2(a0A.x, a0A.y);
        Ahl[f0][akh * 4 + 1][am] = make_float2(a0A.z, a0A.w);
        Ahl[f0][akh * 4 + 2][am] = make_float2(a0B.x, a0B.y);
        Ahl[f0][akh * 4 + 3][am] = make_float2(a0B.z, a0B.w);
        Ahl[f1][akh * 4 + 0][am] = make_float2(a1A.x, a1A.y);
        Ahl[f1][akh * 4 + 1][am] = make_float2(a1A.z, a1A.w);
        Ahl[f1][akh * 4 + 2][am] = make_float2(a1B.x, a1B.y);
        Ahl[f1][akh * 4 + 3][am] = make_float2(a1B.z, a1B.w);
        Bhl[f0][bk][bn] = b0v;
        Bhl[f1][bk][bn] = b1v;
    };

    loadG2(0);
    storeS2(0);
    __syncthreads();

    for (int cc = 0; cc < NPAIR; cc++) {
        if (cc + 1 < NPAIR) loadG2(cc + 1);
        int c = 2 * cc + s;
        int buf = c & 3;

        unsigned ah[2][4], al[2][4];
        #pragma unroll
        for (int i = 0; i < 2; i++) {
            int mb = ww * 32 + i * 16 + gq;
            float2 f0 = Ahl[buf][tq][mb];
            float2 f1 = Ahl[buf][tq][mb + 8];
            float2 f2 = Ahl[buf][tq + 4][mb];
            float2 f3 = Ahl[buf][tq + 4][mb + 8];
            ah[i][0] = __float_as_uint(f0.x); al[i][0] = __float_as_uint(f0.y);
            ah[i][1] = __float_as_uint(f1.x); al[i][1] = __float_as_uint(f1.y);
            ah[i][2] = __float_as_uint(f2.x); al[i][2] = __float_as_uint(f2.y);
            ah[i][3] = __float_as_uint(f3.x); al[i][3] = __float_as_uint(f3.y);
        }
        #pragma unroll
        for (int j = 0; j < 8; j++) {
            int nb = j * 8 + gq;
            float2 bb0 = Bhl[buf][tq][nb];
            float2 bb1 = Bhl[buf][tq + 4][nb];
            unsigned bh0 = __float_as_uint(bb0.x), bl0 = __float_as_uint(bb0.y);
            unsigned bh1 = __float_as_uint(bb1.x), bl1 = __float_as_uint(bb1.y);
            mma_tf32(acc[0][j], ah[0], bh0, bh1);
            mma_tf32(acc[1][j], ah[1], bh0, bh1);
            mma_tf32(acc[0][j], ah[0], bl0, bl1);
            mma_tf32(acc[1][j], ah[1], bl0, bl1);
            mma_tf32(acc[0][j], al[0], bh0, bh1);
            mma_tf32(acc[1][j], al[1], bh0, bh1);
        }
        if (cc + 1 < NPAIR) storeS2(cc + 1);
        __syncthreads();
    }

    // ---- combine warp-set partials: set 1 -> set 0 (two passes of 32 floats) ----
    #pragma unroll
    for (int i = 0; i < 2; i++) {
        if (s == 1) {
            #pragma unroll
            for (int j = 0; j < 8; j++)
                #pragma unroll
                for (int r = 0; r < 4; r++)
                    Xch[(tid - 256) * 33 + j * 4 + r] = acc[i][j][r];
        }
        __syncthreads();
        if (s == 0) {
            #pragma unroll
            for (int j = 0; j < 8; j++)
                #pragma unroll
                for (int r = 0; r < 4; r++)
                    acc[i][j][r] += Xch[tid * 33 + j * 4 + r];
        }
        __syncthreads();
    }

    // ---- epilogue (warp-set 0 computes; all threads hit barriers) ----
    int ns = g_nseg[b];
    if (s == 0) {
        float bs[2][2];
        #pragma unroll
        for (int i = 0; i < 2; i++) {
            bs[i][0] = bias[ww * 32 + i * 16 + gq];
            bs[i][1] = bias[ww * 32 + i * 16 + gq + 8];
        }
        float s1[8][2], s2[8][2];
        #pragma unroll
        for (int j = 0; j < 8; j++) { s1[j][0] = s1[j][1] = s2[j][0] = s2[j][1] = 0.f; }
        #pragma unroll
        for (int i = 0; i < 2; i++)
            #pragma unroll
            for (int j = 0; j < 8; j++) {
                float x0 = fmaxf(acc[i][j][0] + bs[i][0], 0.f);
                float x1 = fmaxf(acc[i][j][1] + bs[i][0], 0.f);
                float x2 = fmaxf(acc[i][j][2] + bs[i][1], 0.f);
                float x3 = fmaxf(acc[i][j][3] + bs[i][1], 0.f);
                acc[i][j][0] = x0; acc[i][j][1] = x1;
                acc[i][j][2] = x2; acc[i][j][3] = x3;
                s1[j][0] += x0 + x2;  s1[j][1] += x1 + x3;
                s2[j][0] += x0 * x0 + x2 * x2;
                s2[j][1] += x1 * x1 + x3 * x3;
            }
        #pragma unroll
        for (int o = 4; o < 32; o <<= 1) {
            #pragma unroll
            for (int j = 0; j < 8; j++) {
                s1[j][0] += __shfl_xor_sync(0xffffffffu, s1[j][0], o);
                s1[j][1] += __shfl_xor_sync(0xffffffffu, s1[j][1], o);
                s2[j][0] += __shfl_xor_sync(0xffffffffu, s2[j][0], o);
                s2[j][1] += __shfl_xor_sync(0xffffffffu, s2[j][1], o);
            }
        }
        if (l < 4) {
            #pragma unroll
            for (int j = 0; j < 8; j++) {
                redA[ww][j * 8 + 2 * l]     = s1[j][0];
                redA[ww][j * 8 + 2 * l + 1] = s1[j][1];
                redB[ww][j * 8 + 2 * l]     = s2[j][0];
                redB[ww][j * 8 + 2 * l + 1] = s2[j][1];
            }
        }
    }
    __syncthreads();
    if (tid < 64) {
        float S1 = 0.f, S2 = 0.f;
        #pragma unroll
        for (int q = 0; q < 8; q++) { S1 += redA[q][tid]; S2 += redB[q][tid]; }
        float m  = S1 * (1.f / 256.f);
        float vv = S2 * (1.f / 256.f) - m * m;
        mvs[tid] = m;
        rvs[tid] = 1.f / sqrtf(vv + EPS);
    }
    __syncthreads();

    if (PHASE == 0) {
        if (s == 0) {
            float mn[8][2], rv[8][2], mk[8][2];
            #pragma unroll
            for (int j = 0; j < 8; j++) {
                int c0 = j * 8 + 2 * tq;
                mn[j][0] = mvs[c0];     mn[j][1] = mvs[c0 + 1];
                rv[j][0] = rvs[c0];     rv[j][1] = rvs[c0 + 1];
                mk[j][0] = (u0 + c0 < ns) ? 1.f : 0.f;
                mk[j][1] = (u0 + c0 + 1 < ns) ? 1.f : 0.f;
            }
            #pragma unroll
            for (int i = 0; i < 2; i++) {
                int f0 = ww * 32 + i * 16 + gq;
                float ga0 = gamma[f0], be0 = beta[f0];
                float ga1 = gamma[f0 + 8], be1 = beta[f0 + 8];
                #pragma unroll
                for (int j = 0; j < 8; j++) {
                    int cc = u0 + j * 8 + 2 * tq;
                    float o0 = ((acc[i][j][0] - mn[j][0]) * rv[j][0] * ga0 + be0) * mk[j][0];
                    float o1 = ((acc[i][j][1] - mn[j][1]) * rv[j][1] * ga0 + be0) * mk[j][1];
                    float o2 = ((acc[i][j][2] - mn[j][0]) * rv[j][0] * ga1 + be1) * mk[j][0];
                    float o3 = ((acc[i][j][3] - mn[j][1]) * rv[j][1] * ga1 + be1) * mk[j][1];
                    float2 s0 = split2(o0), sp1 = split2(o1);
                    float2 sp2 = split2(o2), sp3 = split2(o3);
                    *(float4*)&g_x1hl[((size_t)b * NF + f0) * NU + cc] =
                        make_float4(s0.x, s0.y, sp1.x, sp1.y);
                    *(float4*)&g_x1hl[((size_t)b * NF + f0 + 8) * NU + cc] =
                        make_float4(sp2.x, sp2.y, sp3.x, sp3.y);
                }
            }
        }
    } else {
        if (s == 0) {
            float mn[8][2], rv[8][2], mk[8][2];
            #pragma unroll
            for (int j = 0; j < 8; j++) {
                int c0 = j * 8 + 2 * tq;
                mn[j][0] = mvs[c0];     mn[j][1] = mvs[c0 + 1];
                rv[j][0] = rvs[c0];     rv[j][1] = rvs[c0 + 1];
                mk[j][0] = (u0 + c0 < ns) ? 1.f : 0.f;
                mk[j][1] = (u0 + c0 + 1 < ns) ? 1.f : 0.f;
            }
            float dp[8][2];
            #pragma unroll
            for (int j = 0; j < 8; j++) { dp[j][0] = 0.f; dp[j][1] = 0.f; }
            #pragma unroll
            for (int i = 0; i < 2; i++) {
                int f0 = ww * 32 + i * 16 + gq;
                float ga0 = gamma[f0], be0 = beta[f0], pw0 = pw[f0];
                float ga1 = gamma[f0 + 8], be1 = beta[f0 + 8], pw1 = pw[f0 + 8];
                #pragma unroll
                for (int j = 0; j < 8; j++) {
                    float n0 = ((acc[i][j][0] - mn[j][0]) * rv[j][0] * ga0 + be0) * mk[j][0];
                    float n1 = ((acc[i][j][1] - mn[j][1]) * rv[j][1] * ga0 + be0) * mk[j][1];
                    float n2 = ((acc[i][j][2] - mn[j][0]) * rv[j][0] * ga1 + be1) * mk[j][0];
                    float n3 = ((acc[i][j][3] - mn[j][1]) * rv[j][1] * ga1 + be1) * mk[j][1];
                    dp[j][0] += n0 * pw0 + n2 * pw1;
                    dp[j][1] += n1 * pw0 + n3 * pw1;
                }
            }
            #pragma unroll
            for (int o = 4; o < 32; o <<= 1) {
                #pragma unroll
                for (int j = 0; j < 8; j++) {
                    dp[j][0] += __shfl_xor_sync(0xffffffffu, dp[j][0], o);
                    dp[j][1] += __shfl_xor_sync(0xffffffffu, dp[j][1], o);
                }
            }
            if (l < 4) {
                #pragma unroll
                for (int j = 0; j < 8; j++) {
                    redA[ww][j * 8 + 2 * l]     = dp[j][0];
                    redA[ww][j * 8 + 2 * l + 1] = dp[j][1];
                }
            }
        }
        __syncthreads();
        if (tid < 64) {
            float S = 0.f;
            #pragma unroll
            for (int q = 0; q < 8; q++) S += redA[q][tid];
            int u = u0 + tid;
            float d = (u < ns) ? ceilf(S + pb[0]) : 0.f;
            g_dpred[b * NU + u] = (int)d;
        }
    }
}

// ---------------- kernel 5: per-batch prefix scan + scatter um2 ----------------
__global__ __launch_bounds__(512) void k_scan(int Tn) {
    int b = blockIdx.x;
    int u = threadIdx.x;
    int lane = u & 31, wid = u >> 5;
    int d = g_dpred[b * NU + u];
    int x = d;
    #pragma unroll
    for (int o = 1; o < 32; o <<= 1) {
        int y = __shfl_up_sync(0xffffffffu, x, o);
        if (lane >= o) x += y;
    }
    __shared__ int wt[16];
    if (lane == 31) wt[wid] = x;
    __syncthreads();
    if (u < 16) {
        int t = wt[u];
        #pragma unroll
        for (int o = 1; o < 16; o <<= 1) {
            int y = __shfl_up_sync(0xffffu, t, o);
            if (u >= o) t += y;
        }
        wt[u] = t;
    }
    __syncthreads();
    int csum = x + (wid ? wt[wid - 1] : 0);
    int prev = csum - d;
    int lo = prev > 0 ? prev : 0;
    int hi = csum < Tn ? csum : Tn;
    for (int p = lo; p < hi; p++)
        atomicAdd(&g_um2[b * Tn + p], u + 1);
}

// ---------------- kernel 6: expand + interp -> output ----------------
__global__ __launch_bounds__(256) void k_out(const float* __restrict__ mel,
                                             float* __restrict__ out,
                                             int Tn, int total) {
    int i = blockIdx.x * blockDim.x + threadIdx.x;
    if (i >= total) return;
    int perb = NOUTC * Tn;
    int b = i / perb;
    int r = i - b * perb;
    int ch = r / Tn;
    int t = r - ch * Tn;
    if (ch < 2 * NC) {
        int v = g_um2[b * Tn + t];
        int um = g_umax;
        int idx = v < um ? v : um;   // jax gather clamp semantics
        float val = 0.f;
        if (idx > 0) {
            const float* P = (ch < NC) ? g_uc : g_up;
            int c = (ch < NC) ? ch : ch - NC;
            val = P[((size_t)b * NC + c) * NU + idx - 1];
        }
        out[i] = val;
    } else {
        int mch = ch - 2 * NC;
        float scale = (float)(2048.0 / (double)Tn);
        float src = ((float)t + 0.5f) * scale - 0.5f;
        src = fminf(fmaxf(src, 0.f), (float)(NT - 1));
        int i0 = (int)floorf(src);
        int i1 = i0 + 1 < NT - 1 ? i0 + 1 : NT - 1;
        float w = src - (float)i0;
        const float* mr = mel + ((size_t)b * NMEL + mch) * NT;
        out[i] = mr[i0] * (1.f - w) + mr[i1] * w;
    }
}

// ---------------- launch ----------------
extern "C" void kernel_launch(void* const* d_in, const int* in_sizes, int n_in,
                              void* d_out, int out_size) {
    const float* emb_c  = (const float*)d_in[0];
    const float* emb_p  = (const float*)d_in[1];
    const float* mel    = (const float*)d_in[2];
    const float* g      = (const float*)d_in[3];
    const float* c1w    = (const float*)d_in[4];
    const float* c1b    = (const float*)d_in[5];
    const float* l1g    = (const float*)d_in[6];
    const float* l1b    = (const float*)d_in[7];
    const float* c2w    = (const float*)d_in[8];
    const float* c2b    = (const float*)d_in[9];
    const float* l2g    = (const float*)d_in[10];
    const float* l2b    = (const float*)d_in[11];
    const float* pw     = (const float*)d_in[12];
    const float* pb     = (const float*)d_in[13];
    const float* cw     = (const float*)d_in[14];
    const float* cb     = (const float*)d_in[15];
    const int*   ph     = (const int*)d_in[16];
    float* out = (float*)d_out;

    int Tn = out_size / (NB * NOUTC);

    cudaFuncSetAttribute(k_conv<0>, cudaFuncAttributeMaxDynamicSharedMemorySize, SM_TOTAL);
    cudaFuncSetAttribute(k_conv<1>, cudaFuncAttributeMaxDynamicSharedMemorySize, SM_TOTAL);

    k_zero<<<(NB * Tn + 255) / 256 + 1, 256>>>(Tn);
    k_wsplit<<<(NF * KTOT + 255) / 256, 256>>>(c1w, c2w);
    k_prep<<<2 * NB, 1024>>>(ph, g, cw, cb);
    k_pool<<<dim3(2 * NC / 4, NB), 256>>>(emb_c, emb_p);
    k_conv<0><<<dim3(NU / 64, NB), 512, SM_TOTAL>>>(c1b, l1g, l1b, pw, pb);
    k_conv<1><<<dim3(NU / 64, NB), 512, SM_TOTAL>>>(c2b, l2g, l2b, pw, pb);
    k_scan<<<NB, NU>>>(Tn);
    k_out<<<(out_size + 255) / 256, 256>>>(mel, out, Tn, out_size);
}

// round 13
// speedup vs baseline: 1.1145x; 1.1145x over previous
#include <cuda_runtime.h>
#include <math.h>
#include <stdint.h>

#define NB 16
#define NT 2048
#define NC 256
#define NF 256
#define NU 512
#define NMEL 80
#define NOUTC 592           // 2*NC + NMEL
#define KTOT 768            // NC * 3 taps
#define BK 16               // k per chunk (2 x k8 MMA steps)
#define NCH (KTOT / BK)     // 48
#define UM2CAP 8192
#define EPS 1e-5f
#define AP2 260             // Ahl row pad (float2); 520 words, %32=8
#define BP2 68              // Bhl row pad (float2); 136 words, %32=8

// dynamic smem carve (bytes)
#define SM_AHL   0
#define SM_BHL   (2 * BK * AP2 * 8)                    // 66560
#define SM_TOTAL (SM_BHL + 2 * BK * BP2 * 8)           // 83968
// epilogue aliases (mainloop finished before use)
#define SM_REDA  0                                     // float[8][64]
#define SM_REDB  2048
#define SM_MVS   4096
#define SM_RVS   4352

// ---------------- static device scratch ----------------
__device__ int   g_starts[NB*NU];
__device__ int   g_dur[NB*NU];
__device__ int   g_nseg[NB];
__device__ int   g_umax;
__device__ float g_cgv[NB*NC];
__device__ float g_uc[NB*NC*NU];
__device__ float g_up[NB*NC*NU];
__device__ float g_x0[NB*NC*NU];        // conv1 input: (u_c + cond) * mask
__device__ float g_x1[NB*NF*NU];        // LN1 output * mask  -> conv2 input
__device__ int   g_dpred[NB*NU];
__device__ int   g_um2[NB*UM2CAP];

__device__ __forceinline__ unsigned f2tf32(float x) {
    unsigned r; asm("cvt.rna.tf32.f32 %0, %1;" : "=r"(r) : "f"(x)); return r;
}
__device__ __forceinline__ float2 split2(float x) {
    float h = __uint_as_float(f2tf32(x));
    return make_float2(h, __uint_as_float(f2tf32(x - h)));
}
__device__ __forceinline__ void mma_tf32(float* c, const unsigned* a,
                                         unsigned b0, unsigned b1) {
    asm("mma.sync.aligned.m16n8k8.row.col.f32.tf32.tf32.f32 "
        "{%0,%1,%2,%3}, {%4,%5,%6,%7}, {%8,%9}, {%0,%1,%2,%3};"
        : "+f"(c[0]), "+f"(c[1]), "+f"(c[2]), "+f"(c[3])
        : "r"(a[0]), "r"(a[1]), "r"(a[2]), "r"(a[3]), "r"(b0), "r"(b1));
}

// ---------------- kernel 1: fused dedup (blocks 0..15) + cond (blocks 16..31) ----------------
__global__ __launch_bounds__(1024) void k_prep(const int* __restrict__ ph,
                                               const float* __restrict__ g,
                                               const float* __restrict__ cw,
                                               const float* __restrict__ cb) {
    int blk = blockIdx.x;
    if (blk < NB) {
        int b = blk;
        const int* p = ph + (size_t)b * NT;
        int tid = threadIdx.x;
        int lane = tid & 31, wid = tid >> 5;
        int i0 = 2 * tid, i1 = 2 * tid + 1;
        int p0 = p[i0], p1 = p[i1];
        int pm1 = (i0 > 0) ? p[i0 - 1] : 0;
        int f0 = (i0 == 0) || (p0 != pm1);
        int f1 = (p1 != p0);
        int tsum = f0 + f1;
        int ws = tsum;
        #pragma unroll
        for (int o = 1; o < 32; o <<= 1) {
            int y = __shfl_up_sync(0xffffffffu, ws, o);
            if (lane >= o) ws += y;
        }
        __shared__ int wt[32];
        if (lane == 31) wt[wid] = ws;
        __syncthreads();
        if (wid == 0) {
            int t = wt[lane];
            #pragma unroll
            for (int o = 1; o < 32; o <<= 1) {
                int y = __shfl_up_sync(0xffffffffu, t, o);
                if (lane >= o) t += y;
            }
            wt[lane] = t;
        }
        __syncthreads();
        int base = (wid ? wt[wid - 1] : 0) + (ws - tsum);
        int incl0 = base + f0;
        int incl1 = base + f0 + f1;
        if (f0) g_starts[b * NU + incl0 - 1] = i0;
        if (f1) g_starts[b * NU + incl1 - 1] = i1;
        int ns = wt[31];
        __syncthreads();
        for (int u = tid; u < NU; u += 1024) {
            if (u < ns) {
                int st = g_starts[b * NU + u];
                int en = (u + 1 < ns) ? g_starts[b * NU + u + 1] : NT;
                g_dur[b * NU + u] = en - st;
            } else {
                g_dur[b * NU + u] = 0;
            }
        }
        if (tid == 0) g_nseg[b] = ns;
    } else {
        int b = blk - NB;
        int c = threadIdx.x;
        __shared__ float gs[NC];
        if (c < NC) gs[c] = g[(size_t)b * NC + c];
        __syncthreads();
        if (c < NC) {
            float acc = 0.f;
            const float* row = cw + (size_t)c * NC;
            #pragma unroll 8
            for (int gi = 0; gi < NC; gi++) acc += row[gi] * gs[gi];
            g_cgv[b * NC + c] = acc + cb[c];
        }
    }
}

// ---------------- kernel 2: mean pool (4 channels / block) ----------------
__global__ __launch_bounds__(256) void k_pool(const float* __restrict__ ec,
                                              const float* __restrict__ ep) {
    int b  = blockIdx.y;
    int c0 = blockIdx.x * 4;
    bool isC = (c0 < NC);
    const float* base = isC ? ec + ((size_t)b * NC + c0) * NT
                            : ep + ((size_t)b * NC + (c0 - NC)) * NT;
    __shared__ float rows[4][NT];
    const float4* s4 = (const float4*)base;
    float4* r4 = (float4*)&rows[0][0];
    #pragma unroll
    for (int i = threadIdx.x; i < 4 * NT / 4; i += 256) r4[i] = s4[i];
    __syncthreads();
    int ns = g_nseg[b];
    for (int u = threadIdx.x; u < NU; u += 256) {
        float m[4] = {0.f, 0.f, 0.f, 0.f};
        if (u < ns) {
            int st = g_starts[b * NU + u];
            int d  = g_dur[b * NU + u];
            float inv = 1.f / (float)d;
            #pragma unroll
            for (int r = 0; r < 4; r++) {
                float s = 0.f;
                for (int i = 0; i < d; i++) s += rows[r][st + i];
                m[r] = s * inv;
            }
        }
        #pragma unroll
        for (int r = 0; r < 4; r++) {
            int cc = c0 + r;
            if (isC) {
                float cond = g_cgv[b * NC + cc];
                g_uc[((size_t)b * NC + cc) * NU + u] = m[r];
                g_x0[((size_t)b * NC + cc) * NU + u] = (u < ns) ? (m[r] + cond) : 0.f;
            } else {
                g_up[((size_t)b * NC + (cc - NC)) * NU + u] = m[r];
            }
        }
    }
}

// ---------------- conv GEMM via 3xTF32 mma.sync (256x64x768), BK=16 ----------------
// R9 mapping: 8 warps, warp w: rows w*32..+31 (2 m16 frags), all 64 cols (8 n8 frags).
// Each chunk covers 16 k = two k8 MMA steps, double-buffered, one barrier per chunk.
// (hi,lo) interleaved float2 smem -> fragment loads are LDS.64. In-loop tf32 split.
// PHASE 0: X=g_x0, epilogue = bias+relu+LN1*mask -> g_x1
// PHASE 1: X=g_x1, epilogue = bias+relu+LN2*mask -> proj -> ceil -> g_dpred
template<int PHASE>
__global__ __launch_bounds__(256) void k_conv(const float* __restrict__ W,
                                              const float* __restrict__ bias,
                                              const float* __restrict__ gamma,
                                              const float* __restrict__ beta,
                                              const float* __restrict__ pw,
                                              const float* __restrict__ pb) {
    extern __shared__ char smraw[];
    float2 (*Ahl)[BK][AP2] = (float2 (*)[BK][AP2])(smraw + SM_AHL);
    float2 (*Bhl)[BK][BP2] = (float2 (*)[BK][BP2])(smraw + SM_BHL);
    float (*redA)[64] = (float (*)[64])(smraw + SM_REDA);
    float (*redB)[64] = (float (*)[64])(smraw + SM_REDB);
    float* mvs = (float*)(smraw + SM_MVS);
    float* rvs = (float*)(smraw + SM_RVS);

    int b  = blockIdx.y;
    int u0 = blockIdx.x * 64;
    int tid = threadIdx.x;
    int w  = tid >> 5;
    int l  = tid & 31;
    int gq = l >> 2;        // 0..7
    int tq = l & 3;         // 0..3
    const float* X = PHASE ? g_x1 : g_x0;
    const float* Xb = X + (size_t)b * NC * NU;

    float acc[2][8][4];
    #pragma unroll
    for (int i = 0; i < 2; i++)
        #pragma unroll
        for (int j = 0; j < 8; j++)
            #pragma unroll
            for (int r = 0; r < 4; r++) acc[i][j][r] = 0.f;

    // loaders (256 threads): A: thread = W row tid, 16 k. B: bkk=tid>>4 (k), bnn=(tid&15)*4 (4 cols)
    int bkk = tid >> 4;
    int bnn = (tid & 15) * 4;
    float4 aA, aB, aC, aD;
    float  bv[4];

    auto loadG = [&](int k0) {
        const float4* wr = (const float4*)&W[(size_t)tid * KTOT + k0];
        aA = wr[0]; aB = wr[1]; aC = wr[2]; aD = wr[3];
        int kg  = k0 + bkk;
        int c   = kg / 3;
        int tap = kg - 3 * c;
        const float* xr = Xb + (size_t)c * NU;
        int p0 = u0 + bnn + tap - 1;
        #pragma unroll
        for (int q = 0; q < 4; q++) {
            int pos = p0 + q;
            bv[q] = (pos >= 0 && pos < NU) ? xr[pos] : 0.f;
        }
    };
    auto storeS = [&](int buf) {
        float wv[16] = {aA.x, aA.y, aA.z, aA.w, aB.x, aB.y, aB.z, aB.w,
                        aC.x, aC.y, aC.z, aC.w, aD.x, aD.y, aD.z, aD.w};
        #pragma unroll
        for (int kk = 0; kk < BK; kk++)
            Ahl[buf][kk][tid] = split2(wv[kk]);
        #pragma unroll
        for (int q = 0; q < 4; q++)
            Bhl[buf][bkk][bnn + q] = split2(bv[q]);
    };

    loadG(0);
    storeS(0);
    __syncthreads();

    for (int cc = 0; cc < NCH; cc++) {
        int buf = cc & 1;
        if (cc + 1 < NCH) loadG((cc + 1) * BK);

        #pragma unroll
        for (int step = 0; step < 2; step++) {
            int S = step * 8;
            unsigned ah[2][4], al[2][4];
            #pragma unroll
            for (int i = 0; i < 2; i++) {
                int mb = w * 32 + i * 16 + gq;
                float2 f0 = Ahl[buf][S + tq][mb];
                float2 f1 = Ahl[buf][S + tq][mb + 8];
                float2 f2 = Ahl[buf][S + tq + 4][mb];
                float2 f3 = Ahl[buf][S + tq + 4][mb + 8];
                ah[i][0] = __float_as_uint(f0.x); al[i][0] = __float_as_uint(f0.y);
                ah[i][1] = __float_as_uint(f1.x); al[i][1] = __float_as_uint(f1.y);
                ah[i][2] = __float_as_uint(f2.x); al[i][2] = __float_as_uint(f2.y);
                ah[i][3] = __float_as_uint(f3.x); al[i][3] = __float_as_uint(f3.y);
            }
            #pragma unroll
            for (int j = 0; j < 8; j++) {
                int nb = j * 8 + gq;
                float2 bb0 = Bhl[buf][S + tq][nb];
                float2 bb1 = Bhl[buf][S + tq + 4][nb];
                unsigned bh0 = __float_as_uint(bb0.x), bl0 = __float_as_uint(bb0.y);
                unsigned bh1 = __float_as_uint(bb1.x), bl1 = __float_as_uint(bb1.y);
                mma_tf32(acc[0][j], ah[0], bh0, bh1);
                mma_tf32(acc[1][j], ah[1], bh0, bh1);
                mma_tf32(acc[0][j], ah[0], bl0, bl1);
                mma_tf32(acc[1][j], ah[1], bl0, bl1);
                mma_tf32(acc[0][j], al[0], bh0, bh1);
                mma_tf32(acc[1][j], al[1], bh0, bh1);
            }
        }
        if (cc + 1 < NCH) storeS(buf ^ 1);
        __syncthreads();
    }

    // ---- epilogue (R9): thread rows f(i,0)=w*32+i*16+gq, f(i,1)=+8; cols col(j,s)=j*8+2*tq+s ----
    float bs[2][2];
    #pragma unroll
    for (int i = 0; i < 2; i++) {
        bs[i][0] = bias[w * 32 + i * 16 + gq];
        bs[i][1] = bias[w * 32 + i * 16 + gq + 8];
    }
    float s1[8][2], s2[8][2];
    #pragma unroll
    for (int j = 0; j < 8; j++) { s1[j][0] = s1[j][1] = s2[j][0] = s2[j][1] = 0.f; }
    #pragma unroll
    for (int i = 0; i < 2; i++)
        #pragma unroll
        for (int j = 0; j < 8; j++) {
            float x0 = fmaxf(acc[i][j][0] + bs[i][0], 0.f);
            float x1 = fmaxf(acc[i][j][1] + bs[i][0], 0.f);
            float x2 = fmaxf(acc[i][j][2] + bs[i][1], 0.f);
            float x3 = fmaxf(acc[i][j][3] + bs[i][1], 0.f);
            acc[i][j][0] = x0; acc[i][j][1] = x1;
            acc[i][j][2] = x2; acc[i][j][3] = x3;
            s1[j][0] += x0 + x2;  s1[j][1] += x1 + x3;
            s2[j][0] += x0 * x0 + x2 * x2;
            s2[j][1] += x1 * x1 + x3 * x3;
        }
    #pragma unroll
    for (int o = 4; o < 32; o <<= 1) {
        #pragma unroll
        for (int j = 0; j < 8; j++) {
            s1[j][0] += __shfl_xor_sync(0xffffffffu, s1[j][0], o);
            s1[j][1] += __shfl_xor_sync(0xffffffffu, s1[j][1], o);
            s2[j][0] += __shfl_xor_sync(0xffffffffu, s2[j][0], o);
            s2[j][1] += __shfl_xor_sync(0xffffffffu, s2[j][1], o);
        }
    }
    if (l < 4) {
        #pragma unroll
        for (int j = 0; j < 8; j++) {
            redA[w][j * 8 + 2 * l]     = s1[j][0];
            redA[w][j * 8 + 2 * l + 1] = s1[j][1];
            redB[w][j * 8 + 2 * l]     = s2[j][0];
            redB[w][j * 8 + 2 * l + 1] = s2[j][1];
        }
    }
    __syncthreads();
    if (tid < 64) {
        float S1 = 0.f, S2 = 0.f;
        #pragma unroll
        for (int q = 0; q < 8; q++) { S1 += redA[q][tid]; S2 += redB[q][tid]; }
        float m  = S1 * (1.f / 256.f);
        float vv = S2 * (1.f / 256.f) - m * m;
        mvs[tid] = m;
        rvs[tid] = 1.f / sqrtf(vv + EPS);
    }
    __syncthreads();

    int ns = g_nseg[b];
    float mn[8][2], rv[8][2], mk[8][2];
    #pragma unroll
    for (int j = 0; j < 8; j++) {
        int c0 = j * 8 + 2 * tq;
        mn[j][0] = mvs[c0];     mn[j][1] = mvs[c0 + 1];
        rv[j][0] = rvs[c0];     rv[j][1] = rvs[c0 + 1];
        mk[j][0] = (u0 + c0 < ns) ? 1.f : 0.f;
        mk[j][1] = (u0 + c0 + 1 < ns) ? 1.f : 0.f;
    }

    if (PHASE == 0) {
        #pragma unroll
        for (int i = 0; i < 2; i++) {
            int f0 = w * 32 + i * 16 + gq;
            float ga0 = gamma[f0], be0 = beta[f0];
            float ga1 = gamma[f0 + 8], be1 = beta[f0 + 8];
            #pragma unroll
            for (int j = 0; j < 8; j++) {
                int cc = u0 + j * 8 + 2 * tq;
                float o0 = ((acc[i][j][0] - mn[j][0]) * rv[j][0] * ga0 + be0) * mk[j][0];
                float o1 = ((acc[i][j][1] - mn[j][1]) * rv[j][1] * ga0 + be0) * mk[j][1];
                float o2 = ((acc[i][j][2] - mn[j][0]) * rv[j][0] * ga1 + be1) * mk[j][0];
                float o3 = ((acc[i][j][3] - mn[j][1]) * rv[j][1] * ga1 + be1) * mk[j][1];
                *(float2*)&g_x1[((size_t)b * NF + f0) * NU + cc]     = make_float2(o0, o1);
                *(float2*)&g_x1[((size_t)b * NF + f0 + 8) * NU + cc] = make_float2(o2, o3);
            }
        }
    } else {
        float dp[8][2];
        #pragma unroll
        for (int j = 0; j < 8; j++) { dp[j][0] = 0.f; dp[j][1] = 0.f; }
        #pragma unroll
        for (int i = 0; i < 2; i++) {
            int f0 = w * 32 + i * 16 + gq;
            float ga0 = gamma[f0], be0 = beta[f0], pw0 = pw[f0];
            float ga1 = gamma[f0 + 8], be1 = beta[f0 + 8], pw1 = pw[f0 + 8];
            #pragma unroll
            for (int j = 0; j < 8; j++) {
                float n0 = ((acc[i][j][0] - mn[j][0]) * rv[j][0] * ga0 + be0) * mk[j][0];
                float n1 = ((acc[i][j][1] - mn[j][1]) * rv[j][1] * ga0 + be0) * mk[j][1];
                float n2 = ((acc[i][j][2] - mn[j][0]) * rv[j][0] * ga1 + be1) * mk[j][0];
                float n3 = ((acc[i][j][3] - mn[j][1]) * rv[j][1] * ga1 + be1) * mk[j][1];
                dp[j][0] += n0 * pw0 + n2 * pw1;
                dp[j][1] += n1 * pw0 + n3 * pw1;
            }
        }
        #pragma unroll
        for (int o = 4; o < 32; o <<= 1) {
            #pragma unroll
            for (int j = 0; j < 8; j++) {
                dp[j][0] += __shfl_xor_sync(0xffffffffu, dp[j][0], o);
                dp[j][1] += __shfl_xor_sync(0xffffffffu, dp[j][1], o);
            }
        }
        __syncthreads();
        if (l < 4) {
            #pragma unroll
            for (int j = 0; j < 8; j++) {
                redA[w][j * 8 + 2 * l]     = dp[j][0];
                redA[w][j * 8 + 2 * l + 1] = dp[j][1];
            }
        }
        __syncthreads();
        if (tid < 64) {
            float S = 0.f;
            #pragma unroll
            for (int q = 0; q < 8; q++) S += redA[q][tid];
            int u = u0 + tid;
            float d = (u < ns) ? ceilf(S + pb[0]) : 0.f;
            g_dpred[b * NU + u] = (int)d;
        }
    }
}

// ---------------- kernel 5: zero um2 row + umax + per-batch prefix scan + scatter ----------------
__global__ __launch_bounds__(512) void k_scan(int Tn) {
    int b = blockIdx.x;
    // zero this batch's um2 row (owned exclusively by this block)
    for (int p = threadIdx.x; p < Tn; p += 512)
        g_um2[b * Tn + p] = 0;
    if (b == 0 && threadIdx.x == 0) {
        int mx = 0;
        #pragma unroll
        for (int q = 0; q < NB; q++) mx = max(mx, g_nseg[q]);
        g_umax = mx;
    }
    __syncthreads();
    int u = threadIdx.x;
    int lane = u & 31, wid = u >> 5;
    int d = g_dpred[b * NU + u];
    int x = d;
    #pragma unroll
    for (int o = 1; o < 32; o <<= 1) {
        int y = __shfl_up_sync(0xffffffffu, x, o);
        if (lane >= o) x += y;
    }
    __shared__ int wt[16];
    if (lane == 31) wt[wid] = x;
    __syncthreads();
    if (u < 16) {
        int t = wt[u];
        #pragma unroll
        for (int o = 1; o < 16; o <<= 1) {
            int y = __shfl_up_sync(0xffffu, t, o);
            if (u >= o) t += y;
        }
        wt[u] = t;
    }
    __syncthreads();
    int csum = x + (wid ? wt[wid - 1] : 0);
    int prev = csum - d;
    int lo = prev > 0 ? prev : 0;
    int hi = csum < Tn ? csum : Tn;
    for (int p = lo; p < hi; p++)
        atomicAdd(&g_um2[b * Tn + p], u + 1);
}

// ---------------- kernel 6: expand + interp -> output ----------------
__global__ __launch_bounds__(256) void k_out(const float* __restrict__ mel,
                                             float* __restrict__ out,
                                             int Tn, int total) {
    int i = blockIdx.x * blockDim.x + threadIdx.x;
    if (i >= total) return;
    int perb = NOUTC * Tn;
    int b = i / perb;
    int r = i - b * perb;
    int ch = r / Tn;
    int t = r - ch * Tn;
    if (ch < 2 * NC) {
        int v = g_um2[b * Tn + t];
        int um = g_umax;
        int idx = v < um ? v : um;   // jax gather clamp semantics
        float val = 0.f;
        if (idx > 0) {
            const float* P = (ch < NC) ? g_uc : g_up;
            int c = (ch < NC) ? ch : ch - NC;
            val = P[((size_t)b * NC + c) * NU + idx - 1];
        }
        out[i] = val;
    } else {
        int mch = ch - 2 * NC;
        float scale = (float)(2048.0 / (double)Tn);
        float src = ((float)t + 0.5f) * scale - 0.5f;
        src = fminf(fmaxf(src, 0.f), (float)(NT - 1));
        int i0 = (int)floorf(src);
        int i1 = i0 + 1 < NT - 1 ? i0 + 1 : NT - 1;
        float w = src - (float)i0;
        const float* mr = mel + ((size_t)b * NMEL + mch) * NT;
        out[i] = mr[i0] * (1.f - w) + mr[i1] * w;
    }
}

// ---------------- launch ----------------
extern "C" void kernel_launch(void* const* d_in, const int* in_sizes, int n_in,
                              void* d_out, int out_size) {
    const float* emb_c  = (const float*)d_in[0];
    const float* emb_p  = (const float*)d_in[1];
    const float* mel    = (const float*)d_in[2];
    const float* g      = (const float*)d_in[3];
    const float* c1w    = (const float*)d_in[4];
    const float* c1b    = (const float*)d_in[5];
    const float* l1g    = (const float*)d_in[6];
    const float* l1b    = (const float*)d_in[7];
    const float* c2w    = (const float*)d_in[8];
    const float* c2b    = (const float*)d_in[9];
    const float* l2g    = (const float*)d_in[10];
    const float* l2b    = (const float*)d_in[11];
    const float* pw     = (const float*)d_in[12];
    const float* pb     = (const float*)d_in[13];
    const float* cw     = (const float*)d_in[14];
    const float* cb     = (const float*)d_in[15];
    const int*   ph     = (const int*)d_in[16];
    float* out = (float*)d_out;

    int Tn = out_size / (NB * NOUTC);

    cudaFuncSetAttribute(k_conv<0>, cudaFuncAttributeMaxDynamicSharedMemorySize, SM_TOTAL);
    cudaFuncSetAttribute(k_conv<1>, cudaFuncAttributeMaxDynamicSharedMemorySize, SM_TOTAL);

    k_prep<<<2 * NB, 1024>>>(ph, g, cw, cb);
    k_pool<<<dim3(2 * NC / 4, NB), 256>>>(emb_c, emb_p);
    k_conv<0><<<dim3(NU / 64, NB), 256, SM_TOTAL>>>(c1w, c1b, l1g, l1b, pw, pb);
    k_conv<1><<<dim3(NU / 64, NB), 256, SM_TOTAL>>>(c2w, c2b, l2g, l2b, pw, pb);
    k_scan<<<NB, NU>>>(Tn);
    k_out<<<(out_size + 255) / 256, 256>>>(mel, out, Tn, out_size);
}